// round 8
// baseline (speedup 1.0000x reference)
#include <cuda_runtime.h>
#include <cuda_bf16.h>

// Problem constants (fixed by the dataset)
#define NN      50000
#define EE      800000
#define ET      850000          // EE + NN self loops
#define IN_CH   128
#define HC      256
#define HEADS   4
#define NEG_SLOPE 0.2f
#define LN_EPS  1e-5f

// packed fp32x2 helpers (FFMA2 path — 2x fp32 throughput on sm_103a)
#define FMA2(d, a, b, c) \
    asm("fma.rn.f32x2 %0, %1, %2, %3;" : "=l"(d) : "l"(a), "l"(b), "l"(c))
#define PACK2(d, x, y) \
    asm("mov.b64 %0, {%1, %2};" : "=l"(d) : "r"(__float_as_uint(x)), "r"(__float_as_uint(y)))
#define UNPACK2(x, y, d) \
    asm("mov.b64 {%0, %1}, %2;" : "=r"(x), "=r"(y) : "l"(d))

typedef unsigned long long ull;

// ---------------- device scratch (static, no runtime alloc) ----------------
__device__ float g_h[(size_t)NN * HC];       // 51.2 MB  h = x@W
__device__ float g_as[NN * HEADS];           // per-node att_src dot
__device__ float g_ad[NN * HEADS];           // per-node att_dst dot
__device__ int   g_deg[NN];
__device__ int   g_off[NN + 1];
__device__ int   g_cur[NN];
__device__ int   g_src[ET];                  // sorted-by-dst source node ids

// ---------------- K1: init degree = 1 (self loop) ----------------
__global__ void k_init() {
    int i = blockIdx.x * blockDim.x + threadIdx.x;
    if (i < NN) g_deg[i] = 1;
}

// ---------------- K2: histogram of dst ----------------
__global__ void k_hist(const int* __restrict__ ei) {
    int i = blockIdx.x * blockDim.x + threadIdx.x;
    if (i < EE) {
        int dst = ei[EE + i];
        if (dst >= 0 && dst < NN) atomicAdd(&g_deg[dst], 1);
    }
}

// ---------------- K3: single-block exclusive scan ----------------
__global__ void k_scan() {
    __shared__ int s[1024];
    const int CH = (NN + 1023) / 1024;   // 49
    int t = threadIdx.x;
    int base = t * CH;
    int sum = 0;
    for (int j = 0; j < CH; j++) {
        int i = base + j;
        if (i < NN) sum += g_deg[i];
    }
    s[t] = sum;
    __syncthreads();
    for (int o = 1; o < 1024; o <<= 1) {
        int v = (t >= o) ? s[t - o] : 0;
        __syncthreads();
        s[t] += v;
        __syncthreads();
    }
    int run = (t == 0) ? 0 : s[t - 1];
    for (int j = 0; j < CH; j++) {
        int i = base + j;
        if (i < NN) {
            g_off[i] = run;
            g_cur[i] = run;
            run += g_deg[i];
        }
    }
    if (t == 0) g_off[NN] = s[1023];
}

// ---------------- K4: GEMM h = x@W (row-pair FFMA2), 128x64x16 tiles --------
// grid (391, 4): blockIdx.y = head (64 cols). 256 threads.
// micro tile: 4 row-pairs x 4 cols; tx=t&15 -> half-warp B broadcast (2 wf).
#define BM 128
#define BN 64
#define BK 16
#define APITCH 132

__global__ __launch_bounds__(256) void k_gemm(const float* __restrict__ x,
                                              const float* __restrict__ W,
                                              const float* __restrict__ att_s,
                                              const float* __restrict__ att_d) {
    __shared__ float As[2][BK * APITCH];   // transposed: As[k][row]
    __shared__ float Bs[2][BK * BN];       // Bs[k][col]
    int t  = threadIdx.x;
    int bm = blockIdx.x * BM;
    int head = blockIdx.y;
    int bn = head * BN;
    int tx = t & 15;          // col group (cols bn + tx*4 .. +3)
    int ty = t >> 4;          // row group (rows bm + ty*8 .. +7)
    int ar = t >> 1;          // A-load row 0..127
    int ak = (t & 1) * 8;     // A-load k offset (0 or 8)
    int br = t >> 4;          // B-load k row 0..15
    int bc = (t & 15) * 4;    // B-load col

    ull acc[4][4] = {};       // [row-pair][col], packed fp32

    // preload tile 0
    {
        float4 a0 = make_float4(0.f, 0.f, 0.f, 0.f);
        float4 a1 = make_float4(0.f, 0.f, 0.f, 0.f);
        int row = bm + ar;
        if (row < NN) {
            a0 = *(const float4*)(x + (size_t)row * IN_CH + ak);
            a1 = *(const float4*)(x + (size_t)row * IN_CH + ak + 4);
        }
        As[0][(ak + 0) * APITCH + ar] = a0.x;
        As[0][(ak + 1) * APITCH + ar] = a0.y;
        As[0][(ak + 2) * APITCH + ar] = a0.z;
        As[0][(ak + 3) * APITCH + ar] = a0.w;
        As[0][(ak + 4) * APITCH + ar] = a1.x;
        As[0][(ak + 5) * APITCH + ar] = a1.y;
        As[0][(ak + 6) * APITCH + ar] = a1.z;
        As[0][(ak + 7) * APITCH + ar] = a1.w;
        *(float4*)(Bs[0] + br * BN + bc) =
            *(const float4*)(W + (size_t)br * HC + bn + bc);
    }
    __syncthreads();

    int buf = 0;
    #pragma unroll
    for (int t8 = 0; t8 < 8; t8++) {
        float4 a0, a1, bv;
        if (t8 < 7) {
            int kk = (t8 + 1) * BK;
            a0 = make_float4(0.f, 0.f, 0.f, 0.f);
            a1 = make_float4(0.f, 0.f, 0.f, 0.f);
            int row = bm + ar;
            if (row < NN) {
                a0 = *(const float4*)(x + (size_t)row * IN_CH + kk + ak);
                a1 = *(const float4*)(x + (size_t)row * IN_CH + kk + ak + 4);
            }
            bv = *(const float4*)(W + (size_t)(kk + br) * HC + bn + bc);
        }
        const float* Ab = As[buf];
        const float* Bb = Bs[buf];
        #pragma unroll
        for (int k = 0; k < BK; k++) {
            ulonglong2 A0 = *(const ulonglong2*)(Ab + k * APITCH + ty * 8);
            ulonglong2 A1 = *(const ulonglong2*)(Ab + k * APITCH + ty * 8 + 4);
            float4 b = *(const float4*)(Bb + k * BN + tx * 4);
            ull bb0, bb1, bb2, bb3;
            PACK2(bb0, b.x, b.x);
            PACK2(bb1, b.y, b.y);
            PACK2(bb2, b.z, b.z);
            PACK2(bb3, b.w, b.w);
            FMA2(acc[0][0], A0.x, bb0, acc[0][0]);
            FMA2(acc[0][1], A0.x, bb1, acc[0][1]);
            FMA2(acc[0][2], A0.x, bb2, acc[0][2]);
            FMA2(acc[0][3], A0.x, bb3, acc[0][3]);
            FMA2(acc[1][0], A0.y, bb0, acc[1][0]);
            FMA2(acc[1][1], A0.y, bb1, acc[1][1]);
            FMA2(acc[1][2], A0.y, bb2, acc[1][2]);
            FMA2(acc[1][3], A0.y, bb3, acc[1][3]);
            FMA2(acc[2][0], A1.x, bb0, acc[2][0]);
            FMA2(acc[2][1], A1.x, bb1, acc[2][1]);
            FMA2(acc[2][2], A1.x, bb2, acc[2][2]);
            FMA2(acc[2][3], A1.x, bb3, acc[2][3]);
            FMA2(acc[3][0], A1.y, bb0, acc[3][0]);
            FMA2(acc[3][1], A1.y, bb1, acc[3][1]);
            FMA2(acc[3][2], A1.y, bb2, acc[3][2]);
            FMA2(acc[3][3], A1.y, bb3, acc[3][3]);
        }
        if (t8 < 7) {
            int nb = buf ^ 1;
            As[nb][(ak + 0) * APITCH + ar] = a0.x;
            As[nb][(ak + 1) * APITCH + ar] = a0.y;
            As[nb][(ak + 2) * APITCH + ar] = a0.z;
            As[nb][(ak + 3) * APITCH + ar] = a0.w;
            As[nb][(ak + 4) * APITCH + ar] = a1.x;
            As[nb][(ak + 5) * APITCH + ar] = a1.y;
            As[nb][(ak + 6) * APITCH + ar] = a1.z;
            As[nb][(ak + 7) * APITCH + ar] = a1.w;
            *(float4*)(Bs[nb] + br * BN + bc) = bv;
            __syncthreads();
            buf = nb;
        }
    }

    // epilogue: unpack row-pairs, store h, fused attention dot for this head
    int lane = t & 31;
    float4 sa = *(const float4*)(att_s + head * 64 + tx * 4);
    float4 da = *(const float4*)(att_d + head * 64 + tx * 4);

    #pragma unroll
    for (int p = 0; p < 4; p++) {
        unsigned int l0, h0, l1, h1, l2, h2, l3, h3;
        UNPACK2(l0, h0, acc[p][0]);
        UNPACK2(l1, h1, acc[p][1]);
        UNPACK2(l2, h2, acc[p][2]);
        UNPACK2(l3, h3, acc[p][3]);
        float4 c0 = make_float4(__uint_as_float(l0), __uint_as_float(l1),
                                __uint_as_float(l2), __uint_as_float(l3));
        float4 c1 = make_float4(__uint_as_float(h0), __uint_as_float(h1),
                                __uint_as_float(h2), __uint_as_float(h3));
        int row0 = bm + ty * 8 + 2 * p;
        #pragma unroll
        for (int r = 0; r < 2; r++) {
            float4 c = r ? c1 : c0;
            int row = row0 + r;
            if (row < NN)
                *(float4*)(g_h + (size_t)row * HC + bn + tx * 4) = c;
            float ps = c.x * sa.x + c.y * sa.y + c.z * sa.z + c.w * sa.w;
            float pd = c.x * da.x + c.y * da.y + c.z * da.z + c.w * da.w;
            // reduce over the 16 lanes of this half-warp (one full head)
            ps += __shfl_xor_sync(0xffffffffu, ps, 1);
            ps += __shfl_xor_sync(0xffffffffu, ps, 2);
            ps += __shfl_xor_sync(0xffffffffu, ps, 4);
            ps += __shfl_xor_sync(0xffffffffu, ps, 8);
            pd += __shfl_xor_sync(0xffffffffu, pd, 1);
            pd += __shfl_xor_sync(0xffffffffu, pd, 2);
            pd += __shfl_xor_sync(0xffffffffu, pd, 4);
            pd += __shfl_xor_sync(0xffffffffu, pd, 8);
            if ((lane & 15) == 0 && row < NN) {
                g_as[row * HEADS + head] = ps;
                g_ad[row * HEADS + head] = pd;
            }
        }
    }
}

// ---------------- K6: counting-sort scatter (src permutation only) ----------
__global__ void k_scatter(const int* __restrict__ ei) {
    int i = blockIdx.x * blockDim.x + threadIdx.x;
    if (i >= ET) return;
    int src, dst;
    if (i < EE) { src = ei[i]; dst = ei[EE + i]; }
    else        { src = dst = i - EE; }
    if (src < 0 || src >= NN || dst < 0 || dst >= NN) return;
    int pos = atomicAdd(&g_cur[dst], 1);
    g_src[pos] = src;
}

// ---------------- K7: warp-per-node softmax-aggregate + LN + ELU ------------
// lane owns 8 channels (head = lane>>3). 4-edge unrolled, loads front-batched.
__global__ __launch_bounds__(256, 3) void k_agg(const float* __restrict__ bias,
                                                const float* __restrict__ gamma,
                                                const float* __restrict__ beta,
                                                float* __restrict__ out) {
    int lane = threadIdx.x & 31;
    int n = blockIdx.x * 8 + (threadIdx.x >> 5);
    if (n >= NN) return;
    int start = g_off[n];
    int end   = g_off[n + 1];
    int head  = lane >> 3;
    int cb    = lane * 8;                    // first channel this lane owns
    float ad  = g_ad[n * HEADS + head];      // dst half, fixed per node/head

    float4 acc0 = make_float4(0.f, 0.f, 0.f, 0.f);
    float4 acc1 = make_float4(0.f, 0.f, 0.f, 0.f);
    float wsum = 0.f;

    int e = start;
    for (; e + 4 <= end; e += 4) {
        int s0 = __ldg(&g_src[e]);
        int s1 = __ldg(&g_src[e + 1]);
        int s2 = __ldg(&g_src[e + 2]);
        int s3 = __ldg(&g_src[e + 3]);
        float v0 = __ldg(&g_as[s0 * HEADS + head]);
        float v1 = __ldg(&g_as[s1 * HEADS + head]);
        float v2 = __ldg(&g_as[s2 * HEADS + head]);
        float v3 = __ldg(&g_as[s3 * HEADS + head]);
        const float4* hp0 = (const float4*)(g_h + (size_t)s0 * HC + cb);
        const float4* hp1 = (const float4*)(g_h + (size_t)s1 * HC + cb);
        const float4* hp2 = (const float4*)(g_h + (size_t)s2 * HC + cb);
        const float4* hp3 = (const float4*)(g_h + (size_t)s3 * HC + cb);
        float4 p0 = __ldg(hp0), p1 = __ldg(hp0 + 1);
        float4 q0 = __ldg(hp1), q1 = __ldg(hp1 + 1);
        float4 r0 = __ldg(hp2), r1 = __ldg(hp2 + 1);
        float4 u0 = __ldg(hp3), u1 = __ldg(hp3 + 1);
        v0 += ad; v0 = v0 > 0.f ? v0 : NEG_SLOPE * v0;
        v1 += ad; v1 = v1 > 0.f ? v1 : NEG_SLOPE * v1;
        v2 += ad; v2 = v2 > 0.f ? v2 : NEG_SLOPE * v2;
        v3 += ad; v3 = v3 > 0.f ? v3 : NEG_SLOPE * v3;
        float w0 = __expf(v0), w1 = __expf(v1);
        float w2 = __expf(v2), w3 = __expf(v3);
        wsum += (w0 + w1) + (w2 + w3);
        acc0.x += w0 * p0.x; acc0.y += w0 * p0.y; acc0.z += w0 * p0.z; acc0.w += w0 * p0.w;
        acc1.x += w0 * p1.x; acc1.y += w0 * p1.y; acc1.z += w0 * p1.z; acc1.w += w0 * p1.w;
        acc0.x += w1 * q0.x; acc0.y += w1 * q0.y; acc0.z += w1 * q0.z; acc0.w += w1 * q0.w;
        acc1.x += w1 * q1.x; acc1.y += w1 * q1.y; acc1.z += w1 * q1.z; acc1.w += w1 * q1.w;
        acc0.x += w2 * r0.x; acc0.y += w2 * r0.y; acc0.z += w2 * r0.z; acc0.w += w2 * r0.w;
        acc1.x += w2 * r1.x; acc1.y += w2 * r1.y; acc1.z += w2 * r1.z; acc1.w += w2 * r1.w;
        acc0.x += w3 * u0.x; acc0.y += w3 * u0.y; acc0.z += w3 * u0.z; acc0.w += w3 * u0.w;
        acc1.x += w3 * u1.x; acc1.y += w3 * u1.y; acc1.z += w3 * u1.z; acc1.w += w3 * u1.w;
    }
    for (; e < end; e++) {
        int s0 = __ldg(&g_src[e]);
        float v0 = __ldg(&g_as[s0 * HEADS + head]) + ad;
        v0 = v0 > 0.f ? v0 : NEG_SLOPE * v0;
        float w0 = __expf(v0);
        wsum += w0;
        const float4* hp0 = (const float4*)(g_h + (size_t)s0 * HC + cb);
        float4 p0 = __ldg(hp0), p1 = __ldg(hp0 + 1);
        acc0.x += w0 * p0.x; acc0.y += w0 * p0.y; acc0.z += w0 * p0.z; acc0.w += w0 * p0.w;
        acc1.x += w0 * p1.x; acc1.y += w0 * p1.y; acc1.z += w0 * p1.z; acc1.w += w0 * p1.w;
    }

    float inv = 1.f / (wsum + 1e-16f);
    float4 b0 = ((const float4*)bias)[lane * 2];
    float4 b1 = ((const float4*)bias)[lane * 2 + 1];
    acc0.x = acc0.x * inv + b0.x; acc0.y = acc0.y * inv + b0.y;
    acc0.z = acc0.z * inv + b0.z; acc0.w = acc0.w * inv + b0.w;
    acc1.x = acc1.x * inv + b1.x; acc1.y = acc1.y * inv + b1.y;
    acc1.z = acc1.z * inv + b1.z; acc1.w = acc1.w * inv + b1.w;

    // LayerNorm over all 256 channels (warp reduce)
    float ss  = acc0.x + acc0.y + acc0.z + acc0.w + acc1.x + acc1.y + acc1.z + acc1.w;
    float ss2 = acc0.x * acc0.x + acc0.y * acc0.y + acc0.z * acc0.z + acc0.w * acc0.w
              + acc1.x * acc1.x + acc1.y * acc1.y + acc1.z * acc1.z + acc1.w * acc1.w;
    #pragma unroll
    for (int o = 16; o; o >>= 1) {
        ss  += __shfl_xor_sync(0xffffffffu, ss,  o);
        ss2 += __shfl_xor_sync(0xffffffffu, ss2, o);
    }
    float mu  = ss * (1.f / (float)HC);
    float var = ss2 * (1.f / (float)HC) - mu * mu;
    float r = rsqrtf(var + LN_EPS);

    float4 g0 = ((const float4*)gamma)[lane * 2];
    float4 g1 = ((const float4*)gamma)[lane * 2 + 1];
    float4 e0 = ((const float4*)beta)[lane * 2];
    float4 e1 = ((const float4*)beta)[lane * 2 + 1];
    float4 o0, o1;
    o0.x = (acc0.x - mu) * r * g0.x + e0.x;
    o0.y = (acc0.y - mu) * r * g0.y + e0.y;
    o0.z = (acc0.z - mu) * r * g0.z + e0.z;
    o0.w = (acc0.w - mu) * r * g0.w + e0.w;
    o1.x = (acc1.x - mu) * r * g1.x + e1.x;
    o1.y = (acc1.y - mu) * r * g1.y + e1.y;
    o1.z = (acc1.z - mu) * r * g1.z + e1.z;
    o1.w = (acc1.w - mu) * r * g1.w + e1.w;
    o0.x = o0.x > 0.f ? o0.x : (__expf(o0.x) - 1.f);
    o0.y = o0.y > 0.f ? o0.y : (__expf(o0.y) - 1.f);
    o0.z = o0.z > 0.f ? o0.z : (__expf(o0.z) - 1.f);
    o0.w = o0.w > 0.f ? o0.w : (__expf(o0.w) - 1.f);
    o1.x = o1.x > 0.f ? o1.x : (__expf(o1.x) - 1.f);
    o1.y = o1.y > 0.f ? o1.y : (__expf(o1.y) - 1.f);
    o1.z = o1.z > 0.f ? o1.z : (__expf(o1.z) - 1.f);
    o1.w = o1.w > 0.f ? o1.w : (__expf(o1.w) - 1.f);
    ((float4*)out)[(size_t)n * 64 + lane * 2]     = o0;
    ((float4*)out)[(size_t)n * 64 + lane * 2 + 1] = o1;
}

// ---------------- launch ----------------
extern "C" void kernel_launch(void* const* d_in, const int* in_sizes, int n_in,
                              void* d_out, int out_size) {
    const float* x     = (const float*)d_in[0];
    const int*   ei    = (const int*)d_in[1];
    const float* W     = (const float*)d_in[2];
    const float* att_s = (const float*)d_in[3];
    const float* att_d = (const float*)d_in[4];
    const float* bias  = (const float*)d_in[5];
    const float* gamma = (const float*)d_in[6];
    const float* beta  = (const float*)d_in[7];
    float*       out   = (float*)d_out;

    k_init<<<(NN + 255) / 256, 256>>>();
    k_hist<<<(EE + 255) / 256, 256>>>(ei);
    k_scan<<<1, 1024>>>();
    dim3 gg((NN + BM - 1) / BM, HC / BN);
    k_gemm<<<gg, 256>>>(x, W, att_s, att_d);
    k_scatter<<<(ET + 255) / 256, 256>>>(ei);
    k_agg<<<(NN + 7) / 8, 256>>>(bias, gamma, beta, out);
}

// round 9
// speedup vs baseline: 1.0701x; 1.0701x over previous
#include <cuda_runtime.h>
#include <cuda_bf16.h>

// Problem constants (fixed by the dataset)
#define NN      50000
#define EE      800000
#define ET      850000          // EE + NN self loops
#define IN_CH   128
#define HC      256
#define HEADS   4
#define NEG_SLOPE 0.2f
#define LN_EPS  1e-5f

// packed fp32x2 helpers (FFMA2 path — 2x fp32 throughput on sm_103a)
#define FMA2(d, a, b, c) \
    asm("fma.rn.f32x2 %0, %1, %2, %3;" : "=l"(d) : "l"(a), "l"(b), "l"(c))
#define PACK2(d, x, y) \
    asm("mov.b64 %0, {%1, %2};" : "=l"(d) : "r"(__float_as_uint(x)), "r"(__float_as_uint(y)))
#define UNPACK2(x, y, d) \
    asm("mov.b64 {%0, %1}, %2;" : "=r"(x), "=r"(y) : "l"(d))

typedef unsigned long long ull;

// ---------------- device scratch (static, no runtime alloc) ----------------
__device__ float g_h[(size_t)NN * HC];       // 51.2 MB  h = x@W
__device__ float g_as[NN * HEADS];           // per-node att_src dot
__device__ float g_ad[NN * HEADS];           // per-node att_dst dot
__device__ int   g_deg[NN];
__device__ int   g_off[NN + 1];
__device__ int   g_cur[NN];
__device__ int   g_src[ET];                  // sorted-by-dst source node ids

// ---------------- K1: init degree = 1 (self loop) ----------------
__global__ void k_init() {
    int i = blockIdx.x * blockDim.x + threadIdx.x;
    if (i < NN) g_deg[i] = 1;
}

// ---------------- K2: histogram of dst ----------------
__global__ void k_hist(const int* __restrict__ ei) {
    int i = blockIdx.x * blockDim.x + threadIdx.x;
    if (i < EE) {
        int dst = ei[EE + i];
        if (dst >= 0 && dst < NN) atomicAdd(&g_deg[dst], 1);
    }
}

// ---------------- K3: single-block exclusive scan ----------------
__global__ void k_scan() {
    __shared__ int s[1024];
    const int CH = (NN + 1023) / 1024;   // 49
    int t = threadIdx.x;
    int base = t * CH;
    int sum = 0;
    for (int j = 0; j < CH; j++) {
        int i = base + j;
        if (i < NN) sum += g_deg[i];
    }
    s[t] = sum;
    __syncthreads();
    for (int o = 1; o < 1024; o <<= 1) {
        int v = (t >= o) ? s[t - o] : 0;
        __syncthreads();
        s[t] += v;
        __syncthreads();
    }
    int run = (t == 0) ? 0 : s[t - 1];
    for (int j = 0; j < CH; j++) {
        int i = base + j;
        if (i < NN) {
            g_off[i] = run;
            g_cur[i] = run;
            run += g_deg[i];
        }
    }
    if (t == 0) g_off[NN] = s[1023];
}

// ---------------- K4: GEMM h = x@W (row-pair FFMA2, double-buffered) --------
// 64x128 block tile, BK=16, 256 threads; micro tile = 4 row-pairs x 4 cols.
// (R7 configuration — measured 71.0us)
#define BM 64
#define BN 128
#define BK 16
#define APITCH 68

__global__ __launch_bounds__(256) void k_gemm(const float* __restrict__ x,
                                              const float* __restrict__ W,
                                              const float* __restrict__ att_s,
                                              const float* __restrict__ att_d) {
    __shared__ float As[2][BK * APITCH];   // transposed: As[k][row]
    __shared__ float Bs[2][BK * BN];       // Bs[k][col]
    int t  = threadIdx.x;
    int bm = blockIdx.x * BM;
    int bn = blockIdx.y * BN;
    int tx = t & 31;          // col group (cols bn + tx*4 .. +3)
    int ty = t >> 5;          // row group (rows ty*8 .. ty*8+7)
    int lr = t >> 2;          // A-load row 0..63
    int lk = (t & 3) * 4;     // A-load k offset
    int wr = t >> 5;          // B-load k row 0..7
    int wc = (t & 31) * 4;    // B-load col

    ull acc[4][4] = {};       // [row-pair][col], packed fp32

    // preload tile 0
    {
        float4 av = make_float4(0.f, 0.f, 0.f, 0.f);
        int row = bm + lr;
        if (row < NN) av = *(const float4*)(x + (size_t)row * IN_CH + lk);
        As[0][(lk + 0) * APITCH + lr] = av.x;
        As[0][(lk + 1) * APITCH + lr] = av.y;
        As[0][(lk + 2) * APITCH + lr] = av.z;
        As[0][(lk + 3) * APITCH + lr] = av.w;
        *(float4*)(Bs[0] + wr * BN + wc) =
            *(const float4*)(W + (size_t)wr * HC + bn + wc);
        *(float4*)(Bs[0] + (wr + 8) * BN + wc) =
            *(const float4*)(W + (size_t)(wr + 8) * HC + bn + wc);
    }
    __syncthreads();

    int buf = 0;
    #pragma unroll
    for (int t8 = 0; t8 < 8; t8++) {
        float4 av, bv0, bv1;
        if (t8 < 7) {
            int kk = (t8 + 1) * BK;
            av = make_float4(0.f, 0.f, 0.f, 0.f);
            int row = bm + lr;
            if (row < NN) av = *(const float4*)(x + (size_t)row * IN_CH + kk + lk);
            bv0 = *(const float4*)(W + (size_t)(kk + wr) * HC + bn + wc);
            bv1 = *(const float4*)(W + (size_t)(kk + wr + 8) * HC + bn + wc);
        }
        const float* Ab = As[buf];
        const float* Bb = Bs[buf];
        #pragma unroll
        for (int k = 0; k < BK; k++) {
            ulonglong2 A0 = *(const ulonglong2*)(Ab + k * APITCH + ty * 8);
            ulonglong2 A1 = *(const ulonglong2*)(Ab + k * APITCH + ty * 8 + 4);
            float4 b = *(const float4*)(Bb + k * BN + tx * 4);
            ull bb0, bb1, bb2, bb3;
            PACK2(bb0, b.x, b.x);
            PACK2(bb1, b.y, b.y);
            PACK2(bb2, b.z, b.z);
            PACK2(bb3, b.w, b.w);
            FMA2(acc[0][0], A0.x, bb0, acc[0][0]);
            FMA2(acc[0][1], A0.x, bb1, acc[0][1]);
            FMA2(acc[0][2], A0.x, bb2, acc[0][2]);
            FMA2(acc[0][3], A0.x, bb3, acc[0][3]);
            FMA2(acc[1][0], A0.y, bb0, acc[1][0]);
            FMA2(acc[1][1], A0.y, bb1, acc[1][1]);
            FMA2(acc[1][2], A0.y, bb2, acc[1][2]);
            FMA2(acc[1][3], A0.y, bb3, acc[1][3]);
            FMA2(acc[2][0], A1.x, bb0, acc[2][0]);
            FMA2(acc[2][1], A1.x, bb1, acc[2][1]);
            FMA2(acc[2][2], A1.x, bb2, acc[2][2]);
            FMA2(acc[2][3], A1.x, bb3, acc[2][3]);
            FMA2(acc[3][0], A1.y, bb0, acc[3][0]);
            FMA2(acc[3][1], A1.y, bb1, acc[3][1]);
            FMA2(acc[3][2], A1.y, bb2, acc[3][2]);
            FMA2(acc[3][3], A1.y, bb3, acc[3][3]);
        }
        if (t8 < 7) {
            int nb = buf ^ 1;
            As[nb][(lk + 0) * APITCH + lr] = av.x;
            As[nb][(lk + 1) * APITCH + lr] = av.y;
            As[nb][(lk + 2) * APITCH + lr] = av.z;
            As[nb][(lk + 3) * APITCH + lr] = av.w;
            *(float4*)(Bs[nb] + wr * BN + wc) = bv0;
            *(float4*)(Bs[nb] + (wr + 8) * BN + wc) = bv1;
            __syncthreads();
            buf = nb;
        }
    }

    // epilogue: unpack row-pairs, store h, fused attention dots
    int head = (bn >> 6) + (tx >> 4);          // 64 cols per head
    int coff = (tx & 15) * 4;                  // channel offset within head
    float4 sa = *(const float4*)(att_s + head * 64 + coff);
    float4 da = *(const float4*)(att_d + head * 64 + coff);

    #pragma unroll
    for (int p = 0; p < 4; p++) {
        unsigned int l0, h0, l1, h1, l2, h2, l3, h3;
        UNPACK2(l0, h0, acc[p][0]);
        UNPACK2(l1, h1, acc[p][1]);
        UNPACK2(l2, h2, acc[p][2]);
        UNPACK2(l3, h3, acc[p][3]);
        float4 c0 = make_float4(__uint_as_float(l0), __uint_as_float(l1),
                                __uint_as_float(l2), __uint_as_float(l3));
        float4 c1 = make_float4(__uint_as_float(h0), __uint_as_float(h1),
                                __uint_as_float(h2), __uint_as_float(h3));
        int row0 = bm + ty * 8 + 2 * p;
        #pragma unroll
        for (int r = 0; r < 2; r++) {
            float4 c = r ? c1 : c0;
            int row = row0 + r;
            if (row < NN)
                *(float4*)(g_h + (size_t)row * HC + bn + tx * 4) = c;
            float ps = c.x * sa.x + c.y * sa.y + c.z * sa.z + c.w * sa.w;
            float pd = c.x * da.x + c.y * da.y + c.z * da.z + c.w * da.w;
            #pragma unroll
            for (int o = 1; o < 16; o <<= 1) {
                ps += __shfl_xor_sync(0xffffffffu, ps, o);
                pd += __shfl_xor_sync(0xffffffffu, pd, o);
            }
            if ((tx & 15) == 0 && row < NN) {
                g_as[row * HEADS + head] = ps;
                g_ad[row * HEADS + head] = pd;
            }
        }
    }
}

// ---------------- K6: counting-sort scatter (src permutation only) ----------
__global__ void k_scatter(const int* __restrict__ ei) {
    int i = blockIdx.x * blockDim.x + threadIdx.x;
    if (i >= ET) return;
    int src, dst;
    if (i < EE) { src = ei[i]; dst = ei[EE + i]; }
    else        { src = dst = i - EE; }
    if (src < 0 || src >= NN || dst < 0 || dst >= NN) return;
    int pos = atomicAdd(&g_cur[dst], 1);
    g_src[pos] = src;
}

// ---------------- K7: 2-warps-per-node softmax-aggregate + LN + ELU ---------
// Warp pair (n, half): each warp handles ALL edges but only 128 channels.
// lane owns 4 channels; head = cb>>6. 4-edge unrolled, loads front-batched.
__global__ __launch_bounds__(256) void k_agg(const float* __restrict__ bias,
                                             const float* __restrict__ gamma,
                                             const float* __restrict__ beta,
                                             float* __restrict__ out) {
    __shared__ float s_ss[8], s_ss2[8];
    int t = threadIdx.x;
    int warp = t >> 5, lane = t & 31;
    int n = blockIdx.x * 4 + (warp >> 1);    // NN % 4 == 0: always valid
    int half = warp & 1;
    int start = g_off[n];
    int end   = g_off[n + 1];
    int cb    = half * 128 + lane * 4;       // first of 4 channels this lane owns
    int head  = cb >> 6;
    float ad  = g_ad[n * HEADS + head];

    float4 acc = make_float4(0.f, 0.f, 0.f, 0.f);
    float wsum = 0.f;

    int e = start;
    for (; e + 4 <= end; e += 4) {
        int s0 = __ldg(&g_src[e]);
        int s1 = __ldg(&g_src[e + 1]);
        int s2 = __ldg(&g_src[e + 2]);
        int s3 = __ldg(&g_src[e + 3]);
        float v0 = __ldg(&g_as[s0 * HEADS + head]);
        float v1 = __ldg(&g_as[s1 * HEADS + head]);
        float v2 = __ldg(&g_as[s2 * HEADS + head]);
        float v3 = __ldg(&g_as[s3 * HEADS + head]);
        float4 p = __ldg((const float4*)(g_h + (size_t)s0 * HC + cb));
        float4 q = __ldg((const float4*)(g_h + (size_t)s1 * HC + cb));
        float4 r = __ldg((const float4*)(g_h + (size_t)s2 * HC + cb));
        float4 u = __ldg((const float4*)(g_h + (size_t)s3 * HC + cb));
        v0 += ad; v0 = v0 > 0.f ? v0 : NEG_SLOPE * v0;
        v1 += ad; v1 = v1 > 0.f ? v1 : NEG_SLOPE * v1;
        v2 += ad; v2 = v2 > 0.f ? v2 : NEG_SLOPE * v2;
        v3 += ad; v3 = v3 > 0.f ? v3 : NEG_SLOPE * v3;
        float w0 = __expf(v0), w1 = __expf(v1);
        float w2 = __expf(v2), w3 = __expf(v3);
        wsum += (w0 + w1) + (w2 + w3);
        acc.x += w0 * p.x; acc.y += w0 * p.y; acc.z += w0 * p.z; acc.w += w0 * p.w;
        acc.x += w1 * q.x; acc.y += w1 * q.y; acc.z += w1 * q.z; acc.w += w1 * q.w;
        acc.x += w2 * r.x; acc.y += w2 * r.y; acc.z += w2 * r.z; acc.w += w2 * r.w;
        acc.x += w3 * u.x; acc.y += w3 * u.y; acc.z += w3 * u.z; acc.w += w3 * u.w;
    }
    for (; e < end; e++) {
        int s0 = __ldg(&g_src[e]);
        float v0 = __ldg(&g_as[s0 * HEADS + head]) + ad;
        v0 = v0 > 0.f ? v0 : NEG_SLOPE * v0;
        float w0 = __expf(v0);
        wsum += w0;
        float4 p = __ldg((const float4*)(g_h + (size_t)s0 * HC + cb));
        acc.x += w0 * p.x; acc.y += w0 * p.y; acc.z += w0 * p.z; acc.w += w0 * p.w;
    }

    float inv = 1.f / (wsum + 1e-16f);
    float4 b4 = ((const float4*)bias)[cb >> 2];
    acc.x = acc.x * inv + b4.x; acc.y = acc.y * inv + b4.y;
    acc.z = acc.z * inv + b4.z; acc.w = acc.w * inv + b4.w;

    // LayerNorm moments: warp-reduce over 128 channels, then combine pair
    float ss  = acc.x + acc.y + acc.z + acc.w;
    float ss2 = acc.x * acc.x + acc.y * acc.y + acc.z * acc.z + acc.w * acc.w;
    #pragma unroll
    for (int o = 16; o; o >>= 1) {
        ss  += __shfl_xor_sync(0xffffffffu, ss,  o);
        ss2 += __shfl_xor_sync(0xffffffffu, ss2, o);
    }
    if (lane == 0) { s_ss[warp] = ss; s_ss2[warp] = ss2; }
    __syncthreads();
    float S  = s_ss[warp]  + s_ss[warp ^ 1];
    float S2 = s_ss2[warp] + s_ss2[warp ^ 1];
    float mu  = S * (1.f / (float)HC);
    float var = S2 * (1.f / (float)HC) - mu * mu;
    float r = rsqrtf(var + LN_EPS);

    float4 g4 = ((const float4*)gamma)[cb >> 2];
    float4 e4 = ((const float4*)beta)[cb >> 2];
    float4 o4;
    o4.x = (acc.x - mu) * r * g4.x + e4.x;
    o4.y = (acc.y - mu) * r * g4.y + e4.y;
    o4.z = (acc.z - mu) * r * g4.z + e4.z;
    o4.w = (acc.w - mu) * r * g4.w + e4.w;
    o4.x = o4.x > 0.f ? o4.x : (__expf(o4.x) - 1.f);
    o4.y = o4.y > 0.f ? o4.y : (__expf(o4.y) - 1.f);
    o4.z = o4.z > 0.f ? o4.z : (__expf(o4.z) - 1.f);
    o4.w = o4.w > 0.f ? o4.w : (__expf(o4.w) - 1.f);
    ((float4*)out)[(size_t)n * 64 + (cb >> 2)] = o4;
}

// ---------------- launch ----------------
extern "C" void kernel_launch(void* const* d_in, const int* in_sizes, int n_in,
                              void* d_out, int out_size) {
    const float* x     = (const float*)d_in[0];
    const int*   ei    = (const int*)d_in[1];
    const float* W     = (const float*)d_in[2];
    const float* att_s = (const float*)d_in[3];
    const float* att_d = (const float*)d_in[4];
    const float* bias  = (const float*)d_in[5];
    const float* gamma = (const float*)d_in[6];
    const float* beta  = (const float*)d_in[7];
    float*       out   = (float*)d_out;

    k_init<<<(NN + 255) / 256, 256>>>();
    k_hist<<<(EE + 255) / 256, 256>>>(ei);
    k_scan<<<1, 1024>>>();
    dim3 gg((NN + BM - 1) / BM, HC / BN);
    k_gemm<<<gg, 256>>>(x, W, att_s, att_d);
    k_scatter<<<(ET + 255) / 256, 256>>>(ei);
    k_agg<<<NN / 4, 256>>>(bias, gamma, beta, out);
}

// round 10
// speedup vs baseline: 1.4056x; 1.3135x over previous
#include <cuda_runtime.h>
#include <cuda_fp16.h>

// Problem constants (fixed by the dataset)
#define NN      50000
#define EE      800000
#define ET      850000          // EE + NN self loops
#define IN_CH   128
#define HC      256
#define HEADS   4
#define NEG_SLOPE 0.2f
#define LN_EPS  1e-5f

// packed fp32x2 helpers (FFMA2 path — 2x fp32 throughput on sm_103a)
#define FMA2(d, a, b, c) \
    asm("fma.rn.f32x2 %0, %1, %2, %3;" : "=l"(d) : "l"(a), "l"(b), "l"(c))
#define PACK2(d, x, y) \
    asm("mov.b64 %0, {%1, %2};" : "=l"(d) : "r"(__float_as_uint(x)), "r"(__float_as_uint(y)))
#define UNPACK2(x, y, d) \
    asm("mov.b64 {%0, %1}, %2;" : "=r"(x), "=r"(y) : "l"(d))

typedef unsigned long long ull;

// ---------------- device scratch (static, no runtime alloc) ----------------
__device__ __half g_h[(size_t)NN * HC];      // 25.6 MB  h = x@W (fp16)
__device__ float g_as[NN * HEADS];           // per-node att_src dot (fp32)
__device__ float g_ad[NN * HEADS];           // per-node att_dst dot (fp32)
__device__ int   g_deg[NN];
__device__ int   g_off[NN + 1];
__device__ int   g_cur[NN];
__device__ int   g_src[ET];                  // sorted-by-dst source node ids

// ---------------- K1: init degree = 1 (self loop) ----------------
__global__ void k_init() {
    int i = blockIdx.x * blockDim.x + threadIdx.x;
    if (i < NN) g_deg[i] = 1;
}

// ---------------- K2: histogram of dst ----------------
__global__ void k_hist(const int* __restrict__ ei) {
    int i = blockIdx.x * blockDim.x + threadIdx.x;
    if (i < EE) {
        int dst = ei[EE + i];
        if (dst >= 0 && dst < NN) atomicAdd(&g_deg[dst], 1);
    }
}

// ---------------- K3: coalesced tiled scan (single block, 1024 thr) --------
__global__ void k_scan() {
    __shared__ int warpsum[32];
    int t = threadIdx.x;
    int lane = t & 31, w = t >> 5;
    int carry = 0;
    for (int base = 0; base < NN; base += 1024) {
        int i = base + t;
        int v = (i < NN) ? g_deg[i] : 0;
        // warp inclusive scan
        int sv = v;
        #pragma unroll
        for (int o = 1; o < 32; o <<= 1) {
            int u = __shfl_up_sync(0xffffffffu, sv, o);
            if (lane >= o) sv += u;
        }
        if (lane == 31) warpsum[w] = sv;
        __syncthreads();
        if (w == 0) {
            int u = warpsum[lane];
            #pragma unroll
            for (int o = 1; o < 32; o <<= 1) {
                int z = __shfl_up_sync(0xffffffffu, u, o);
                if (lane >= o) u += z;
            }
            warpsum[lane] = u;
        }
        __syncthreads();
        int woff = (w == 0) ? 0 : warpsum[w - 1];
        int excl = carry + woff + sv - v;
        if (i < NN) { g_off[i] = excl; g_cur[i] = excl; }
        carry += warpsum[31];
        __syncthreads();
    }
    if (t == 0) g_off[NN] = carry;
}

// ---------------- K4: GEMM h = x@W (row-pair FFMA2, double-buffered) --------
// 64x128 block tile, BK=16, 256 threads; micro tile = 4 row-pairs x 4 cols.
#define BM 64
#define BN 128
#define BK 16
#define APITCH 68

__global__ __launch_bounds__(256) void k_gemm(const float* __restrict__ x,
                                              const float* __restrict__ W,
                                              const float* __restrict__ att_s,
                                              const float* __restrict__ att_d) {
    __shared__ float As[2][BK * APITCH];   // transposed: As[k][row]
    __shared__ float Bs[2][BK * BN];       // Bs[k][col]
    int t  = threadIdx.x;
    int bm = blockIdx.x * BM;
    int bn = blockIdx.y * BN;
    int tx = t & 31;          // col group (cols bn + tx*4 .. +3)
    int ty = t >> 5;          // row group (rows ty*8 .. ty*8+7)
    int lr = t >> 2;          // A-load row 0..63
    int lk = (t & 3) * 4;     // A-load k offset
    int wr = t >> 5;          // B-load k row 0..7
    int wc = (t & 31) * 4;    // B-load col

    ull acc[4][4] = {};       // [row-pair][col], packed fp32

    // preload tile 0
    {
        float4 av = make_float4(0.f, 0.f, 0.f, 0.f);
        int row = bm + lr;
        if (row < NN) av = *(const float4*)(x + (size_t)row * IN_CH + lk);
        As[0][(lk + 0) * APITCH + lr] = av.x;
        As[0][(lk + 1) * APITCH + lr] = av.y;
        As[0][(lk + 2) * APITCH + lr] = av.z;
        As[0][(lk + 3) * APITCH + lr] = av.w;
        *(float4*)(Bs[0] + wr * BN + wc) =
            *(const float4*)(W + (size_t)wr * HC + bn + wc);
        *(float4*)(Bs[0] + (wr + 8) * BN + wc) =
            *(const float4*)(W + (size_t)(wr + 8) * HC + bn + wc);
    }
    __syncthreads();

    int buf = 0;
    #pragma unroll
    for (int t8 = 0; t8 < 8; t8++) {
        float4 av, bv0, bv1;
        if (t8 < 7) {
            int kk = (t8 + 1) * BK;
            av = make_float4(0.f, 0.f, 0.f, 0.f);
            int row = bm + lr;
            if (row < NN) av = *(const float4*)(x + (size_t)row * IN_CH + kk + lk);
            bv0 = *(const float4*)(W + (size_t)(kk + wr) * HC + bn + wc);
            bv1 = *(const float4*)(W + (size_t)(kk + wr + 8) * HC + bn + wc);
        }
        const float* Ab = As[buf];
        const float* Bb = Bs[buf];
        #pragma unroll
        for (int k = 0; k < BK; k++) {
            ulonglong2 A0 = *(const ulonglong2*)(Ab + k * APITCH + ty * 8);
            ulonglong2 A1 = *(const ulonglong2*)(Ab + k * APITCH + ty * 8 + 4);
            float4 b = *(const float4*)(Bb + k * BN + tx * 4);
            ull bb0, bb1, bb2, bb3;
            PACK2(bb0, b.x, b.x);
            PACK2(bb1, b.y, b.y);
            PACK2(bb2, b.z, b.z);
            PACK2(bb3, b.w, b.w);
            FMA2(acc[0][0], A0.x, bb0, acc[0][0]);
            FMA2(acc[0][1], A0.x, bb1, acc[0][1]);
            FMA2(acc[0][2], A0.x, bb2, acc[0][2]);
            FMA2(acc[0][3], A0.x, bb3, acc[0][3]);
            FMA2(acc[1][0], A0.y, bb0, acc[1][0]);
            FMA2(acc[1][1], A0.y, bb1, acc[1][1]);
            FMA2(acc[1][2], A0.y, bb2, acc[1][2]);
            FMA2(acc[1][3], A0.y, bb3, acc[1][3]);
            FMA2(acc[2][0], A1.x, bb0, acc[2][0]);
            FMA2(acc[2][1], A1.x, bb1, acc[2][1]);
            FMA2(acc[2][2], A1.x, bb2, acc[2][2]);
            FMA2(acc[2][3], A1.x, bb3, acc[2][3]);
            FMA2(acc[3][0], A1.y, bb0, acc[3][0]);
            FMA2(acc[3][1], A1.y, bb1, acc[3][1]);
            FMA2(acc[3][2], A1.y, bb2, acc[3][2]);
            FMA2(acc[3][3], A1.y, bb3, acc[3][3]);
        }
        if (t8 < 7) {
            int nb = buf ^ 1;
            As[nb][(lk + 0) * APITCH + lr] = av.x;
            As[nb][(lk + 1) * APITCH + lr] = av.y;
            As[nb][(lk + 2) * APITCH + lr] = av.z;
            As[nb][(lk + 3) * APITCH + lr] = av.w;
            *(float4*)(Bs[nb] + wr * BN + wc) = bv0;
            *(float4*)(Bs[nb] + (wr + 8) * BN + wc) = bv1;
            __syncthreads();
            buf = nb;
        }
    }

    // epilogue: unpack row-pairs, store h (fp16), fused attention dots (fp32)
    int head = (bn >> 6) + (tx >> 4);          // 64 cols per head
    int coff = (tx & 15) * 4;                  // channel offset within head
    float4 sa = *(const float4*)(att_s + head * 64 + coff);
    float4 da = *(const float4*)(att_d + head * 64 + coff);

    #pragma unroll
    for (int p = 0; p < 4; p++) {
        unsigned int l0, h0, l1, h1, l2, h2, l3, h3;
        UNPACK2(l0, h0, acc[p][0]);
        UNPACK2(l1, h1, acc[p][1]);
        UNPACK2(l2, h2, acc[p][2]);
        UNPACK2(l3, h3, acc[p][3]);
        float4 c0 = make_float4(__uint_as_float(l0), __uint_as_float(l1),
                                __uint_as_float(l2), __uint_as_float(l3));
        float4 c1 = make_float4(__uint_as_float(h0), __uint_as_float(h1),
                                __uint_as_float(h2), __uint_as_float(h3));
        int row0 = bm + ty * 8 + 2 * p;
        #pragma unroll
        for (int r = 0; r < 2; r++) {
            float4 c = r ? c1 : c0;
            int row = row0 + r;
            if (row < NN) {
                __half2 hA = __floats2half2_rn(c.x, c.y);
                __half2 hB = __floats2half2_rn(c.z, c.w);
                uint2 pk;
                pk.x = *(unsigned int*)&hA;
                pk.y = *(unsigned int*)&hB;
                *(uint2*)(g_h + (size_t)row * HC + bn + tx * 4) = pk;
            }
            float ps = c.x * sa.x + c.y * sa.y + c.z * sa.z + c.w * sa.w;
            float pd = c.x * da.x + c.y * da.y + c.z * da.z + c.w * da.w;
            #pragma unroll
            for (int o = 1; o < 16; o <<= 1) {
                ps += __shfl_xor_sync(0xffffffffu, ps, o);
                pd += __shfl_xor_sync(0xffffffffu, pd, o);
            }
            if ((tx & 15) == 0 && row < NN) {
                g_as[row * HEADS + head] = ps;
                g_ad[row * HEADS + head] = pd;
            }
        }
    }
}

// ---------------- K6: counting-sort scatter (src permutation only) ----------
__global__ void k_scatter(const int* __restrict__ ei) {
    int i = blockIdx.x * blockDim.x + threadIdx.x;
    if (i >= ET) return;
    int src, dst;
    if (i < EE) { src = ei[i]; dst = ei[EE + i]; }
    else        { src = dst = i - EE; }
    if (src < 0 || src >= NN || dst < 0 || dst >= NN) return;
    int pos = atomicAdd(&g_cur[dst], 1);
    g_src[pos] = src;
}

// ---------------- K7: warp-per-node softmax-aggregate + LN + ELU ------------
// g_h is fp16: lane owns 8 channels via ONE 16B load per edge. head = lane>>3.
__global__ __launch_bounds__(256) void k_agg(const float* __restrict__ bias,
                                             const float* __restrict__ gamma,
                                             const float* __restrict__ beta,
                                             float* __restrict__ out) {
    int lane = threadIdx.x & 31;
    int n = blockIdx.x * 8 + (threadIdx.x >> 5);
    if (n >= NN) return;
    int start = g_off[n];
    int end   = g_off[n + 1];
    int head  = lane >> 3;
    int cb    = lane * 8;                    // first channel this lane owns
    float ad  = g_ad[n * HEADS + head];      // dst half, fixed per node/head

    float4 acc0 = make_float4(0.f, 0.f, 0.f, 0.f);
    float4 acc1 = make_float4(0.f, 0.f, 0.f, 0.f);
    float wsum = 0.f;

    int e = start;
    for (; e + 4 <= end; e += 4) {
        int s0 = __ldg(&g_src[e]);
        int s1 = __ldg(&g_src[e + 1]);
        int s2 = __ldg(&g_src[e + 2]);
        int s3 = __ldg(&g_src[e + 3]);
        float v0 = __ldg(&g_as[s0 * HEADS + head]);
        float v1 = __ldg(&g_as[s1 * HEADS + head]);
        float v2 = __ldg(&g_as[s2 * HEADS + head]);
        float v3 = __ldg(&g_as[s3 * HEADS + head]);
        uint4 hv0 = __ldg((const uint4*)(g_h + (size_t)s0 * HC + cb));
        uint4 hv1 = __ldg((const uint4*)(g_h + (size_t)s1 * HC + cb));
        uint4 hv2 = __ldg((const uint4*)(g_h + (size_t)s2 * HC + cb));
        uint4 hv3 = __ldg((const uint4*)(g_h + (size_t)s3 * HC + cb));
        v0 += ad; v0 = v0 > 0.f ? v0 : NEG_SLOPE * v0;
        v1 += ad; v1 = v1 > 0.f ? v1 : NEG_SLOPE * v1;
        v2 += ad; v2 = v2 > 0.f ? v2 : NEG_SLOPE * v2;
        v3 += ad; v3 = v3 > 0.f ? v3 : NEG_SLOPE * v3;
        float w0 = __expf(v0), w1 = __expf(v1);
        float w2 = __expf(v2), w3 = __expf(v3);
        wsum += (w0 + w1) + (w2 + w3);
        {
            float2 f0 = __half22float2(*(__half2*)&hv0.x);
            float2 f1 = __half22float2(*(__half2*)&hv0.y);
            float2 f2 = __half22float2(*(__half2*)&hv0.z);
            float2 f3 = __half22float2(*(__half2*)&hv0.w);
            acc0.x += w0 * f0.x; acc0.y += w0 * f0.y;
            acc0.z += w0 * f1.x; acc0.w += w0 * f1.y;
            acc1.x += w0 * f2.x; acc1.y += w0 * f2.y;
            acc1.z += w0 * f3.x; acc1.w += w0 * f3.y;
        }
        {
            float2 f0 = __half22float2(*(__half2*)&hv1.x);
            float2 f1 = __half22float2(*(__half2*)&hv1.y);
            float2 f2 = __half22float2(*(__half2*)&hv1.z);
            float2 f3 = __half22float2(*(__half2*)&hv1.w);
            acc0.x += w1 * f0.x; acc0.y += w1 * f0.y;
            acc0.z += w1 * f1.x; acc0.w += w1 * f1.y;
            acc1.x += w1 * f2.x; acc1.y += w1 * f2.y;
            acc1.z += w1 * f3.x; acc1.w += w1 * f3.y;
        }
        {
            float2 f0 = __half22float2(*(__half2*)&hv2.x);
            float2 f1 = __half22float2(*(__half2*)&hv2.y);
            float2 f2 = __half22float2(*(__half2*)&hv2.z);
            float2 f3 = __half22float2(*(__half2*)&hv2.w);
            acc0.x += w2 * f0.x; acc0.y += w2 * f0.y;
            acc0.z += w2 * f1.x; acc0.w += w2 * f1.y;
            acc1.x += w2 * f2.x; acc1.y += w2 * f2.y;
            acc1.z += w2 * f3.x; acc1.w += w2 * f3.y;
        }
        {
            float2 f0 = __half22float2(*(__half2*)&hv3.x);
            float2 f1 = __half22float2(*(__half2*)&hv3.y);
            float2 f2 = __half22float2(*(__half2*)&hv3.z);
            float2 f3 = __half22float2(*(__half2*)&hv3.w);
            acc0.x += w3 * f0.x; acc0.y += w3 * f0.y;
            acc0.z += w3 * f1.x; acc0.w += w3 * f1.y;
            acc1.x += w3 * f2.x; acc1.y += w3 * f2.y;
            acc1.z += w3 * f3.x; acc1.w += w3 * f3.y;
        }
    }
    for (; e < end; e++) {
        int s0 = __ldg(&g_src[e]);
        float v0 = __ldg(&g_as[s0 * HEADS + head]) + ad;
        v0 = v0 > 0.f ? v0 : NEG_SLOPE * v0;
        float w0 = __expf(v0);
        wsum += w0;
        uint4 hv0 = __ldg((const uint4*)(g_h + (size_t)s0 * HC + cb));
        float2 f0 = __half22float2(*(__half2*)&hv0.x);
        float2 f1 = __half22float2(*(__half2*)&hv0.y);
        float2 f2 = __half22float2(*(__half2*)&hv0.z);
        float2 f3 = __half22float2(*(__half2*)&hv0.w);
        acc0.x += w0 * f0.x; acc0.y += w0 * f0.y;
        acc0.z += w0 * f1.x; acc0.w += w0 * f1.y;
        acc1.x += w0 * f2.x; acc1.y += w0 * f2.y;
        acc1.z += w0 * f3.x; acc1.w += w0 * f3.y;
    }

    float inv = 1.f / (wsum + 1e-16f);
    float4 b0 = ((const float4*)bias)[lane * 2];
    float4 b1 = ((const float4*)bias)[lane * 2 + 1];
    acc0.x = acc0.x * inv + b0.x; acc0.y = acc0.y * inv + b0.y;
    acc0.z = acc0.z * inv + b0.z; acc0.w = acc0.w * inv + b0.w;
    acc1.x = acc1.x * inv + b1.x; acc1.y = acc1.y * inv + b1.y;
    acc1.z = acc1.z * inv + b1.z; acc1.w = acc1.w * inv + b1.w;

    // LayerNorm over all 256 channels (warp reduce)
    float ss  = acc0.x + acc0.y + acc0.z + acc0.w + acc1.x + acc1.y + acc1.z + acc1.w;
    float ss2 = acc0.x * acc0.x + acc0.y * acc0.y + acc0.z * acc0.z + acc0.w * acc0.w
              + acc1.x * acc1.x + acc1.y * acc1.y + acc1.z * acc1.z + acc1.w * acc1.w;
    #pragma unroll
    for (int o = 16; o; o >>= 1) {
        ss  += __shfl_xor_sync(0xffffffffu, ss,  o);
        ss2 += __shfl_xor_sync(0xffffffffu, ss2, o);
    }
    float mu  = ss * (1.f / (float)HC);
    float var = ss2 * (1.f / (float)HC) - mu * mu;
    float r = rsqrtf(var + LN_EPS);

    float4 g0 = ((const float4*)gamma)[lane * 2];
    float4 g1 = ((const float4*)gamma)[lane * 2 + 1];
    float4 e0 = ((const float4*)beta)[lane * 2];
    float4 e1 = ((const float4*)beta)[lane * 2 + 1];
    float4 o0, o1;
    o0.x = (acc0.x - mu) * r * g0.x + e0.x;
    o0.y = (acc0.y - mu) * r * g0.y + e0.y;
    o0.z = (acc0.z - mu) * r * g0.z + e0.z;
    o0.w = (acc0.w - mu) * r * g0.w + e0.w;
    o1.x = (acc1.x - mu) * r * g1.x + e1.x;
    o1.y = (acc1.y - mu) * r * g1.y + e1.y;
    o1.z = (acc1.z - mu) * r * g1.z + e1.z;
    o1.w = (acc1.w - mu) * r * g1.w + e1.w;
    o0.x = o0.x > 0.f ? o0.x : (__expf(o0.x) - 1.f);
    o0.y = o0.y > 0.f ? o0.y : (__expf(o0.y) - 1.f);
    o0.z = o0.z > 0.f ? o0.z : (__expf(o0.z) - 1.f);
    o0.w = o0.w > 0.f ? o0.w : (__expf(o0.w) - 1.f);
    o1.x = o1.x > 0.f ? o1.x : (__expf(o1.x) - 1.f);
    o1.y = o1.y > 0.f ? o1.y : (__expf(o1.y) - 1.f);
    o1.z = o1.z > 0.f ? o1.z : (__expf(o1.z) - 1.f);
    o1.w = o1.w > 0.f ? o1.w : (__expf(o1.w) - 1.f);
    ((float4*)out)[(size_t)n * 64 + lane * 2]     = o0;
    ((float4*)out)[(size_t)n * 64 + lane * 2 + 1] = o1;
}

// ---------------- launch ----------------
extern "C" void kernel_launch(void* const* d_in, const int* in_sizes, int n_in,
                              void* d_out, int out_size) {
    const float* x     = (const float*)d_in[0];
    const int*   ei    = (const int*)d_in[1];
    const float* W     = (const float*)d_in[2];
    const float* att_s = (const float*)d_in[3];
    const float* att_d = (const float*)d_in[4];
    const float* bias  = (const float*)d_in[5];
    const float* gamma = (const float*)d_in[6];
    const float* beta  = (const float*)d_in[7];
    float*       out   = (float*)d_out;

    k_init<<<(NN + 255) / 256, 256>>>();
    k_hist<<<(EE + 255) / 256, 256>>>(ei);
    k_scan<<<1, 1024>>>();
    dim3 gg((NN + BM - 1) / BM, HC / BN);
    k_gemm<<<gg, 256>>>(x, W, att_s, att_d);
    k_scatter<<<(ET + 255) / 256, 256>>>(ei);
    k_agg<<<(NN + 7) / 8, 256>>>(bias, gamma, beta, out);
}